// round 8
// baseline (speedup 1.0000x reference)
#include <cuda_runtime.h>
#include <math.h>

#define BB 8
#define CC 128
#define NPIX (512*512)           // pixels per batch image
#define SPLIT 16                 // chunks per (b, channel-pair) plane
#define CHUNK (NPIX/SPLIT)       // 16384 elements per chunk
#define EPSV 1e-12f

// ---- scratch (static device arrays; no allocations) ----
__device__ float  g_partC[SPLIT*BB*CC];   // partial masked sums
__device__ float  g_partT[SPLIT*BB*CC];   // partial total sums
__device__ int    g_cntPart[BB*SPLIT];    // partial change counts
__device__ float  g_dvec[BB*CC];          // prototype difference vector
__device__ float  g_valid[BB];

// ---------------- masked + total channel sums, 2 channels/block --------------
// grid: (SPLIT, CC/2, BB), 256 threads. Channels c and c+64 share gt loads.
__global__ void __launch_bounds__(256, 8)
k_sums(const float* __restrict__ fm, const int* __restrict__ gt) {
    int chunk = blockIdx.x, c0 = blockIdx.y, b = blockIdx.z;
    int c1 = c0 + CC/2;
    const float4* f0 = (const float4*)(fm + ((size_t)(b*CC + c0)) * NPIX + (size_t)chunk * CHUNK);
    const float4* f1 = (const float4*)(fm + ((size_t)(b*CC + c1)) * NPIX + (size_t)chunk * CHUNK);
    const int4*   g4 = (const int4*)(gt + (size_t)b * NPIX + (size_t)chunk * CHUNK);

    float sc0 = 0.f, st0 = 0.f, sc1 = 0.f, st1 = 0.f;
    int cnt = 0;
    const int nvec = CHUNK / 4;  // 4096 float4s
    #pragma unroll 4
    for (int j = threadIdx.x; j < nvec; j += 256) {
        float4 v0 = __ldcs(f0 + j);     // evict-first streams
        float4 v1 = __ldcs(f1 + j);
        int4   g  = __ldg(g4 + j);      // L2-resident, shared by 64 blocks
        sc0 += (g.x ? v0.x : 0.f) + (g.y ? v0.y : 0.f) + (g.z ? v0.z : 0.f) + (g.w ? v0.w : 0.f);
        st0 += v0.x + v0.y + v0.z + v0.w;
        sc1 += (g.x ? v1.x : 0.f) + (g.y ? v1.y : 0.f) + (g.z ? v1.z : 0.f) + (g.w ? v1.w : 0.f);
        st1 += v1.x + v1.y + v1.z + v1.w;
        if (c0 == 0) cnt += g.x + g.y + g.z + g.w;   // gt in {0,1}
    }
    #pragma unroll
    for (int o = 16; o; o >>= 1) {
        sc0 += __shfl_down_sync(0xffffffffu, sc0, o);
        st0 += __shfl_down_sync(0xffffffffu, st0, o);
        sc1 += __shfl_down_sync(0xffffffffu, sc1, o);
        st1 += __shfl_down_sync(0xffffffffu, st1, o);
        if (c0 == 0) cnt += __shfl_down_sync(0xffffffffu, cnt, o);
    }
    __shared__ float shc0[8], sht0[8], shc1[8], sht1[8];
    __shared__ int   shn[8];
    int w = threadIdx.x >> 5;
    if ((threadIdx.x & 31) == 0) {
        shc0[w] = sc0; sht0[w] = st0; shc1[w] = sc1; sht1[w] = st1; shn[w] = cnt;
    }
    __syncthreads();
    if (threadIdx.x == 0) {
        float rc0 = 0.f, rt0 = 0.f, rc1 = 0.f, rt1 = 0.f;
        int   rn = 0;
        #pragma unroll
        for (int i = 0; i < 8; i++) {
            rc0 += shc0[i]; rt0 += sht0[i];
            rc1 += shc1[i]; rt1 += sht1[i];
            rn  += shn[i];
        }
        int base = (chunk*BB + b)*CC;
        g_partC[base + c0] = rc0;
        g_partT[base + c0] = rt0;
        g_partC[base + c1] = rc1;
        g_partT[base + c1] = rt1;
        if (c0 == 0) g_cntPart[b*SPLIT + chunk] = rn;
    }
}

// ---------------- prototypes -> difference vector (tiny) ----------------
// grid: BB blocks, CC threads
__global__ void k_proto() {
    int b = blockIdx.x, c = threadIdx.x;
    __shared__ float s_nc;
    if (c < 32) {
        int v = (c < SPLIT) ? g_cntPart[b*SPLIT + c] : 0;
        #pragma unroll
        for (int o = 16; o; o >>= 1) v += __shfl_down_sync(0xffffffffu, v, o);
        if (c == 0) s_nc = (float)v;
    }
    __syncthreads();
    float nc = s_nc;
    float nn = (float)NPIX - nc;

    float sC = 0.f, sT = 0.f;
    #pragma unroll
    for (int k = 0; k < SPLIT; k++) {
        int idx = (k*BB + b)*CC + c;
        sC += g_partC[idx];
        sT += g_partT[idx];
    }
    float pc = sC / fmaxf(nc, 1.f);
    float pn = (sT - sC) / fmaxf(nn, 1.f);

    float s1 = pc*pc, s2 = pn*pn;
    #pragma unroll
    for (int o = 16; o; o >>= 1) {
        s1 += __shfl_down_sync(0xffffffffu, s1, o);
        s2 += __shfl_down_sync(0xffffffffu, s2, o);
    }
    __shared__ float r1[4], r2[4];
    int w = c >> 5;
    if ((c & 31) == 0) { r1[w] = s1; r2[w] = s2; }
    __syncthreads();
    float t1 = r1[0] + r1[1] + r1[2] + r1[3];
    float t2 = r2[0] + r2[1] + r2[2] + r2[3];
    float npc = fmaxf(sqrtf(t1), EPSV);
    float npn = fmaxf(sqrtf(t2), EPSV);
    g_dvec[b*CC + c] = pc / npc - pn / npn;
    if (c == 0) g_valid[b] = (nc > 0.f && nn > 0.f) ? 1.f : 0.f;
}

// ---------------- per-pixel similarity + exp ----------------
// grid: (NPIX/2048, BB), 512 threads, 4 pixels (one float4) per thread.
__global__ void __launch_bounds__(512, 4)
k_out(const float* __restrict__ fm, const int* __restrict__ gt,
      float* __restrict__ out) {
    int b = blockIdx.y;
    __shared__ float sd[CC];
    __shared__ float sval;
    if (threadIdx.x < CC) sd[threadIdx.x] = g_dvec[b*CC + threadIdx.x];
    if (threadIdx.x == 0) sval = g_valid[b];
    __syncthreads();

    int base = blockIdx.x * 512 + threadIdx.x;     // float4 index within plane
    const float4* f4 = (const float4*)(fm + (size_t)b * CC * NPIX);
    const size_t plane = NPIX / 4;                 // float4s per channel plane

    float4 s = {0.f,0.f,0.f,0.f};
    float4 q = {0.f,0.f,0.f,0.f};
    #pragma unroll 8
    for (int c = 0; c < CC; c++) {
        float4 v = __ldcs(f4 + (size_t)c * plane + base);
        float dc = sd[c];
        s.x = fmaf(v.x, dc, s.x);  q.x = fmaf(v.x, v.x, q.x);
        s.y = fmaf(v.y, dc, s.y);  q.y = fmaf(v.y, v.y, q.y);
        s.z = fmaf(v.z, dc, s.z);  q.z = fmaf(v.z, v.z, q.z);
        s.w = fmaf(v.w, dc, s.w);  q.w = fmaf(v.w, v.w, q.w);
    }
    int4 g = __ldg((const int4*)(gt + (size_t)b * NPIX) + base);
    float val = sval;
    float4 o;
    o.x = val * __expf((g.x ? 1.f : -1.f) * s.x * rsqrtf(fmaxf(q.x, 1e-30f)));
    o.y = val * __expf((g.y ? 1.f : -1.f) * s.y * rsqrtf(fmaxf(q.y, 1e-30f)));
    o.z = val * __expf((g.z ? 1.f : -1.f) * s.z * rsqrtf(fmaxf(q.z, 1e-30f)));
    o.w = val * __expf((g.w ? 1.f : -1.f) * s.w * rsqrtf(fmaxf(q.w, 1e-30f)));
    __stcs((float4*)(out + (size_t)b * NPIX) + base, o);   // streaming store
}

extern "C" void kernel_launch(void* const* d_in, const int* in_sizes, int n_in,
                              void* d_out, int out_size) {
    const float* fm = (const float*)d_in[0];
    const int*   gt = (const int*)d_in[1];
    float* out = (float*)d_out;

    {
        dim3 grid(SPLIT, CC/2, BB);
        k_sums<<<grid, 256>>>(fm, gt);
    }
    k_proto<<<BB, CC>>>();
    {
        dim3 grid(NPIX/2048, BB);
        k_out<<<grid, 512>>>(fm, gt, out);
    }
}

// round 9
// speedup vs baseline: 1.0329x; 1.0329x over previous
#include <cuda_runtime.h>
#include <math.h>

#define BB 8
#define CC 128
#define NPIX (512*512)           // pixels per batch image
#define SPLIT 16                 // chunks per (b,c) plane in sum pass
#define CHUNK (NPIX/SPLIT)       // 16384 elements per chunk
#define EPSV 1e-12f

// ---- scratch (static device arrays; no allocations) ----
__device__ float  g_partC[SPLIT*BB*CC];   // partial masked sums
__device__ float  g_partT[SPLIT*BB*CC];   // partial total sums
__device__ int    g_cntPart[BB*SPLIT];    // partial change counts
__device__ float  g_dvec[BB*CC];          // prototype difference vector
__device__ float  g_valid[BB];

// ---------------- masked + total channel sums (+ counts on c==0) -------------
// grid: (SPLIT, CC, BB), 256 threads. Contiguous 64KB fm chunk per block.
// (R5-measured: 152.6us @ 89.8% DRAM — the stable best.)
__global__ void __launch_bounds__(256, 8)
k_sums(const float* __restrict__ fm, const int* __restrict__ gt) {
    int chunk = blockIdx.x, c = blockIdx.y, b = blockIdx.z;
    const float4* f4 = (const float4*)(fm + ((size_t)(b*CC + c)) * NPIX + (size_t)chunk * CHUNK);
    const int4*   g4 = (const int4*)(gt + (size_t)b * NPIX + (size_t)chunk * CHUNK);
    float sc = 0.f, st = 0.f;
    int cnt = 0;
    const int nvec = CHUNK / 4;  // 4096 float4s
    #pragma unroll 4
    for (int j = threadIdx.x; j < nvec; j += 256) {
        float4 v = __ldcs(f4 + j);      // evict-first: pure stream
        int4   g = __ldg(g4 + j);       // L2-resident, reused by 128 blocks
        sc += (g.x ? v.x : 0.f) + (g.y ? v.y : 0.f) + (g.z ? v.z : 0.f) + (g.w ? v.w : 0.f);
        st += v.x + v.y + v.z + v.w;
        if (c == 0) cnt += g.x + g.y + g.z + g.w;   // gt in {0,1}
    }
    #pragma unroll
    for (int o = 16; o; o >>= 1) {
        sc += __shfl_down_sync(0xffffffffu, sc, o);
        st += __shfl_down_sync(0xffffffffu, st, o);
        if (c == 0) cnt += __shfl_down_sync(0xffffffffu, cnt, o);
    }
    __shared__ float shc[8], sht[8];
    __shared__ int   shn[8];
    int w = threadIdx.x >> 5;
    if ((threadIdx.x & 31) == 0) { shc[w] = sc; sht[w] = st; shn[w] = cnt; }
    __syncthreads();
    if (threadIdx.x == 0) {
        float rc = 0.f, rt = 0.f;
        int   rn = 0;
        #pragma unroll
        for (int i = 0; i < 8; i++) { rc += shc[i]; rt += sht[i]; rn += shn[i]; }
        int idx = (chunk*BB + b)*CC + c;
        g_partC[idx] = rc;
        g_partT[idx] = rt;
        if (c == 0) g_cntPart[b*SPLIT + chunk] = rn;
    }
}

// ---------------- prototypes -> difference vector (tiny) ----------------
// grid: BB blocks, CC threads
__global__ void k_proto() {
    int b = blockIdx.x, c = threadIdx.x;
    __shared__ float s_nc;
    if (c < 32) {
        int v = (c < SPLIT) ? g_cntPart[b*SPLIT + c] : 0;
        #pragma unroll
        for (int o = 16; o; o >>= 1) v += __shfl_down_sync(0xffffffffu, v, o);
        if (c == 0) s_nc = (float)v;
    }
    __syncthreads();
    float nc = s_nc;
    float nn = (float)NPIX - nc;

    float sC = 0.f, sT = 0.f;
    #pragma unroll
    for (int k = 0; k < SPLIT; k++) {
        int idx = (k*BB + b)*CC + c;
        sC += g_partC[idx];
        sT += g_partT[idx];
    }
    float pc = sC / fmaxf(nc, 1.f);
    float pn = (sT - sC) / fmaxf(nn, 1.f);

    float s1 = pc*pc, s2 = pn*pn;
    #pragma unroll
    for (int o = 16; o; o >>= 1) {
        s1 += __shfl_down_sync(0xffffffffu, s1, o);
        s2 += __shfl_down_sync(0xffffffffu, s2, o);
    }
    __shared__ float r1[4], r2[4];
    int w = c >> 5;
    if ((c & 31) == 0) { r1[w] = s1; r2[w] = s2; }
    __syncthreads();
    float t1 = r1[0] + r1[1] + r1[2] + r1[3];
    float t2 = r2[0] + r2[1] + r2[2] + r2[3];
    float npc = fmaxf(sqrtf(t1), EPSV);
    float npn = fmaxf(sqrtf(t2), EPSV);
    g_dvec[b*CC + c] = pc / npc - pn / npn;
    if (c == 0) g_valid[b] = (nc > 0.f && nn > 0.f) ? 1.f : 0.f;
}

// ---------------- per-pixel similarity + exp ----------------
// grid: (NPIX/2048, BB), 512 threads, 4 pixels (one float4) per thread.
__global__ void __launch_bounds__(512, 4)
k_out(const float* __restrict__ fm, const int* __restrict__ gt,
      float* __restrict__ out) {
    int b = blockIdx.y;
    __shared__ float sd[CC];
    __shared__ float sval;
    if (threadIdx.x < CC) sd[threadIdx.x] = g_dvec[b*CC + threadIdx.x];
    if (threadIdx.x == 0) sval = g_valid[b];
    __syncthreads();

    int base = blockIdx.x * 512 + threadIdx.x;     // float4 index within plane
    const float4* f4 = (const float4*)(fm + (size_t)b * CC * NPIX);
    const size_t plane = NPIX / 4;                 // float4s per channel plane

    float4 s = {0.f,0.f,0.f,0.f};
    float4 q = {0.f,0.f,0.f,0.f};
    #pragma unroll 8
    for (int c = 0; c < CC; c++) {
        float4 v = __ldcs(f4 + (size_t)c * plane + base);
        float dc = sd[c];
        s.x = fmaf(v.x, dc, s.x);  q.x = fmaf(v.x, v.x, q.x);
        s.y = fmaf(v.y, dc, s.y);  q.y = fmaf(v.y, v.y, q.y);
        s.z = fmaf(v.z, dc, s.z);  q.z = fmaf(v.z, v.z, q.z);
        s.w = fmaf(v.w, dc, s.w);  q.w = fmaf(v.w, v.w, q.w);
    }
    int4 g = __ldg((const int4*)(gt + (size_t)b * NPIX) + base);
    float val = sval;
    float4 o;
    o.x = val * __expf((g.x ? 1.f : -1.f) * s.x * rsqrtf(fmaxf(q.x, 1e-30f)));
    o.y = val * __expf((g.y ? 1.f : -1.f) * s.y * rsqrtf(fmaxf(q.y, 1e-30f)));
    o.z = val * __expf((g.z ? 1.f : -1.f) * s.z * rsqrtf(fmaxf(q.z, 1e-30f)));
    o.w = val * __expf((g.w ? 1.f : -1.f) * s.w * rsqrtf(fmaxf(q.w, 1e-30f)));
    __stcs((float4*)(out + (size_t)b * NPIX) + base, o);   // streaming store
}

extern "C" void kernel_launch(void* const* d_in, const int* in_sizes, int n_in,
                              void* d_out, int out_size) {
    const float* fm = (const float*)d_in[0];
    const int*   gt = (const int*)d_in[1];
    float* out = (float*)d_out;

    {
        dim3 grid(SPLIT, CC, BB);
        k_sums<<<grid, 256>>>(fm, gt);
    }
    k_proto<<<BB, CC>>>();
    {
        dim3 grid(NPIX/2048, BB);
        k_out<<<grid, 512>>>(fm, gt, out);
    }
}